// round 1
// baseline (speedup 1.0000x reference)
#include <cuda_runtime.h>
#include <cuda_bf16.h>
#include <cstddef>

// Problem dims (fixed by the reference)
#define NSRC 4096
#define NTGT 4096
#define DIM  1024

// Scratch (no allocations allowed -> __device__ globals)
__device__ float g_sp[(size_t)NSRC * DIM];   // projected source
__device__ float g_tp[(size_t)NTGT * DIM];   // projected target
__device__ float g_sqs[NSRC];
__device__ float g_sqt[NTGT];
__device__ float g_rowsum[NSRC];

// ---------------------------------------------------------------------------
// NT GEMM with bias: C[r,c] = sum_k A[r,k]*B[c,k] + bias[c]
// A: [M,K] row-major, B: [N,K] row-major, C: [M,N]
// Tiles: 128x128x16, 256 threads, 8x8 per thread.
// ---------------------------------------------------------------------------
__global__ __launch_bounds__(256) void gemm_nt_bias(
    const float* __restrict__ A, const float* __restrict__ B,
    const float* __restrict__ bias, float* __restrict__ C,
    int M, int N, int K)
{
    __shared__ float As[16][128];
    __shared__ float Bs[16][128];
    const int tid = threadIdx.x;
    const int tx = tid & 15, ty = tid >> 4;
    const int rowBase = blockIdx.y * 128;
    const int colBase = blockIdx.x * 128;

    const float* Aptr = A + (size_t)rowBase * K;
    const float* Bptr = B + (size_t)colBase * K;

    float acc[8][8];
#pragma unroll
    for (int i = 0; i < 8; i++)
#pragma unroll
        for (int j = 0; j < 8; j++) acc[i][j] = 0.f;

    for (int kt = 0; kt < K; kt += 16) {
#pragma unroll
        for (int i = 0; i < 2; i++) {
            int v = tid + i * 256;
            int r = v >> 2;
            int c4 = (v & 3) * 4;
            float4 a = *(const float4*)(Aptr + (size_t)r * K + kt + c4);
            As[c4 + 0][r] = a.x; As[c4 + 1][r] = a.y;
            As[c4 + 2][r] = a.z; As[c4 + 3][r] = a.w;
            float4 b = *(const float4*)(Bptr + (size_t)r * K + kt + c4);
            Bs[c4 + 0][r] = b.x; Bs[c4 + 1][r] = b.y;
            Bs[c4 + 2][r] = b.z; Bs[c4 + 3][r] = b.w;
        }
        __syncthreads();
#pragma unroll
        for (int kk = 0; kk < 16; kk++) {
            float4 a0 = *(const float4*)&As[kk][ty * 8];
            float4 a1 = *(const float4*)&As[kk][ty * 8 + 4];
            float4 b0 = *(const float4*)&Bs[kk][tx * 8];
            float4 b1 = *(const float4*)&Bs[kk][tx * 8 + 4];
            float ra[8] = {a0.x, a0.y, a0.z, a0.w, a1.x, a1.y, a1.z, a1.w};
            float rb[8] = {b0.x, b0.y, b0.z, b0.w, b1.x, b1.y, b1.z, b1.w};
#pragma unroll
            for (int i = 0; i < 8; i++)
#pragma unroll
                for (int j = 0; j < 8; j++)
                    acc[i][j] = fmaf(ra[i], rb[j], acc[i][j]);
        }
        __syncthreads();
    }

#pragma unroll
    for (int i = 0; i < 8; i++) {
        int r = rowBase + ty * 8 + i;
#pragma unroll
        for (int j = 0; j < 8; j++) {
            int c = colBase + tx * 8 + j;
            C[(size_t)r * N + c] = acc[i][j] + bias[c];
        }
    }
}

// ---------------------------------------------------------------------------
// NT GEMM with distance/exp epilogue:
//   Ku[r,c] = exp(-sqrt(max(sqa[r] + sqb[c] - 2*dot, 0)) / T)
// ---------------------------------------------------------------------------
__global__ __launch_bounds__(256) void gemm_cost(
    const float* __restrict__ A, const float* __restrict__ B,
    const float* __restrict__ sqa, const float* __restrict__ sqb,
    const float* __restrict__ temp,
    float* __restrict__ C, int M, int N, int K)
{
    __shared__ float As[16][128];
    __shared__ float Bs[16][128];
    const int tid = threadIdx.x;
    const int tx = tid & 15, ty = tid >> 4;
    const int rowBase = blockIdx.y * 128;
    const int colBase = blockIdx.x * 128;

    const float* Aptr = A + (size_t)rowBase * K;
    const float* Bptr = B + (size_t)colBase * K;

    float acc[8][8];
#pragma unroll
    for (int i = 0; i < 8; i++)
#pragma unroll
        for (int j = 0; j < 8; j++) acc[i][j] = 0.f;

    for (int kt = 0; kt < K; kt += 16) {
#pragma unroll
        for (int i = 0; i < 2; i++) {
            int v = tid + i * 256;
            int r = v >> 2;
            int c4 = (v & 3) * 4;
            float4 a = *(const float4*)(Aptr + (size_t)r * K + kt + c4);
            As[c4 + 0][r] = a.x; As[c4 + 1][r] = a.y;
            As[c4 + 2][r] = a.z; As[c4 + 3][r] = a.w;
            float4 b = *(const float4*)(Bptr + (size_t)r * K + kt + c4);
            Bs[c4 + 0][r] = b.x; Bs[c4 + 1][r] = b.y;
            Bs[c4 + 2][r] = b.z; Bs[c4 + 3][r] = b.w;
        }
        __syncthreads();
#pragma unroll
        for (int kk = 0; kk < 16; kk++) {
            float4 a0 = *(const float4*)&As[kk][ty * 8];
            float4 a1 = *(const float4*)&As[kk][ty * 8 + 4];
            float4 b0 = *(const float4*)&Bs[kk][tx * 8];
            float4 b1 = *(const float4*)&Bs[kk][tx * 8 + 4];
            float ra[8] = {a0.x, a0.y, a0.z, a0.w, a1.x, a1.y, a1.z, a1.w};
            float rb[8] = {b0.x, b0.y, b0.z, b0.w, b1.x, b1.y, b1.z, b1.w};
#pragma unroll
            for (int i = 0; i < 8; i++)
#pragma unroll
                for (int j = 0; j < 8; j++)
                    acc[i][j] = fmaf(ra[i], rb[j], acc[i][j]);
        }
        __syncthreads();
    }

    const float invT = 1.0f / temp[0];
#pragma unroll
    for (int i = 0; i < 8; i++) {
        int r = rowBase + ty * 8 + i;
        float sa = sqa[r];
#pragma unroll
        for (int j = 0; j < 8; j++) {
            int c = colBase + tx * 8 + j;
            float d2 = sa + sqb[c] - 2.0f * acc[i][j];
            float cost = sqrtf(fmaxf(d2, 0.0f));
            C[(size_t)r * N + c] = __expf(-cost * invT);
        }
    }
}

// ---------------------------------------------------------------------------
// NN GEMM: C[r,c] = sum_k A[r,k]*B[k,c]
// A: [M,K] row-major, B: [K,N] row-major, C: [M,N]
// ---------------------------------------------------------------------------
__global__ __launch_bounds__(256) void gemm_nn(
    const float* __restrict__ A, const float* __restrict__ B,
    float* __restrict__ C, int M, int N, int K)
{
    __shared__ float As[16][128];
    __shared__ float Bs[16][128];
    const int tid = threadIdx.x;
    const int tx = tid & 15, ty = tid >> 4;
    const int rowBase = blockIdx.y * 128;
    const int colBase = blockIdx.x * 128;

    const float* Aptr = A + (size_t)rowBase * K;

    float acc[8][8];
#pragma unroll
    for (int i = 0; i < 8; i++)
#pragma unroll
        for (int j = 0; j < 8; j++) acc[i][j] = 0.f;

    for (int kt = 0; kt < K; kt += 16) {
#pragma unroll
        for (int i = 0; i < 2; i++) {
            int v = tid + i * 256;
            int r = v >> 2;
            int c4 = (v & 3) * 4;
            float4 a = *(const float4*)(Aptr + (size_t)r * K + kt + c4);
            As[c4 + 0][r] = a.x; As[c4 + 1][r] = a.y;
            As[c4 + 2][r] = a.z; As[c4 + 3][r] = a.w;
            // B tile: 16 k-rows x 128 n-cols, natural layout
            int br = v >> 5;            // 0..15
            int bc4 = (v & 31) * 4;     // 0..124
            float4 b = *(const float4*)(B + (size_t)(kt + br) * N + colBase + bc4);
            *(float4*)&Bs[br][bc4] = b;
        }
        __syncthreads();
#pragma unroll
        for (int kk = 0; kk < 16; kk++) {
            float4 a0 = *(const float4*)&As[kk][ty * 8];
            float4 a1 = *(const float4*)&As[kk][ty * 8 + 4];
            float4 b0 = *(const float4*)&Bs[kk][tx * 8];
            float4 b1 = *(const float4*)&Bs[kk][tx * 8 + 4];
            float ra[8] = {a0.x, a0.y, a0.z, a0.w, a1.x, a1.y, a1.z, a1.w};
            float rb[8] = {b0.x, b0.y, b0.z, b0.w, b1.x, b1.y, b1.z, b1.w};
#pragma unroll
            for (int i = 0; i < 8; i++)
#pragma unroll
                for (int j = 0; j < 8; j++)
                    acc[i][j] = fmaf(ra[i], rb[j], acc[i][j]);
        }
        __syncthreads();
    }

#pragma unroll
    for (int i = 0; i < 8; i++) {
        int r = rowBase + ty * 8 + i;
#pragma unroll
        for (int j = 0; j < 8; j++) {
            int c = colBase + tx * 8 + j;
            C[(size_t)r * N + c] = acc[i][j];
        }
    }
}

// ---------------------------------------------------------------------------
// Deterministic per-row reduction: out[row] = sum_j X[row,j] (or X^2 if SQ)
// One block per row.
// ---------------------------------------------------------------------------
template <bool SQ>
__global__ __launch_bounds__(256) void row_reduce(
    const float* __restrict__ X, float* __restrict__ out, int cols)
{
    const int row = blockIdx.x;
    const float4* p = reinterpret_cast<const float4*>(X + (size_t)row * cols);
    const int n4 = cols >> 2;
    float s = 0.f;
    for (int j = threadIdx.x; j < n4; j += 256) {
        float4 v = p[j];
        if (SQ) s += v.x * v.x + v.y * v.y + v.z * v.z + v.w * v.w;
        else    s += v.x + v.y + v.z + v.w;
    }
    __shared__ float red[256];
    red[threadIdx.x] = s;
    __syncthreads();
#pragma unroll
    for (int st = 128; st > 0; st >>= 1) {
        if (threadIdx.x < st) red[threadIdx.x] += red[threadIdx.x + st];
        __syncthreads();
    }
    if (threadIdx.x == 0) out[row] = red[0];
}

// ---------------------------------------------------------------------------
// Normalize rows of K in place: K[i,j] /= rowsum[i]
// ---------------------------------------------------------------------------
__global__ __launch_bounds__(256) void normalize_rows(
    float* __restrict__ Kmat, const float* __restrict__ rowsum, int ncols)
{
    size_t idx = (size_t)blockIdx.x * blockDim.x + threadIdx.x;  // float4 index
    size_t total4 = ((size_t)NSRC * ncols) >> 2;
    if (idx >= total4) return;
    int row = (int)((idx * 4) / (size_t)ncols);
    float inv = 1.0f / rowsum[row];
    float4* p = reinterpret_cast<float4*>(Kmat) + idx;
    float4 v = *p;
    v.x *= inv; v.y *= inv; v.z *= inv; v.w *= inv;
    *p = v;
}

// ---------------------------------------------------------------------------
// Launch
// ---------------------------------------------------------------------------
extern "C" void kernel_launch(void* const* d_in, const int* in_sizes, int n_in,
                              void* d_out, int out_size)
{
    const float* source = (const float*)d_in[0];
    const float* target = (const float*)d_in[1];
    const float* W_src  = (const float*)d_in[2];
    const float* b_src  = (const float*)d_in[3];
    const float* W_tgt  = (const float*)d_in[4];
    const float* b_tgt  = (const float*)d_in[5];
    const float* temp   = (const float*)d_in[6];

    float* aligned = (float*)d_out;                          // [NSRC, DIM]
    float* Kout    = (float*)d_out + (size_t)NSRC * DIM;     // [NSRC, NTGT]

    float *sp, *tp, *sqs, *sqt, *rs;
    cudaGetSymbolAddress((void**)&sp,  g_sp);
    cudaGetSymbolAddress((void**)&tp,  g_tp);
    cudaGetSymbolAddress((void**)&sqs, g_sqs);
    cudaGetSymbolAddress((void**)&sqt, g_sqt);
    cudaGetSymbolAddress((void**)&rs,  g_rowsum);

    // 1) Projections: sp = source @ W_src^T + b_src ; tp = target @ W_tgt^T + b_tgt
    gemm_nt_bias<<<dim3(DIM / 128, NSRC / 128), 256>>>(source, W_src, b_src, sp, NSRC, DIM, DIM);
    gemm_nt_bias<<<dim3(DIM / 128, NTGT / 128), 256>>>(target, W_tgt, b_tgt, tp, NTGT, DIM, DIM);

    // 2) Squared norms (deterministic block reductions)
    row_reduce<true><<<NSRC, 256>>>(sp, sqs, DIM);
    row_reduce<true><<<NTGT, 256>>>(tp, sqt, DIM);

    // 3) Unnormalized kernel matrix Ku = exp(-cdist/T) into d_out K region
    gemm_cost<<<dim3(NTGT / 128, NSRC / 128), 256>>>(sp, tp, sqs, sqt, temp, Kout, NSRC, NTGT, DIM);

    // 4) Row sums of Ku, then normalize in place
    row_reduce<false><<<NSRC, 256>>>(Kout, rs, NTGT);
    {
        size_t total4 = ((size_t)NSRC * NTGT) >> 2;
        int blocks = (int)((total4 + 255) / 256);
        normalize_rows<<<blocks, 256>>>(Kout, rs, NTGT);
    }

    // 5) aligned = K @ target
    gemm_nn<<<dim3(DIM / 128, NSRC / 128), 256>>>(Kout, target, aligned, NSRC, DIM, NTGT);
}

// round 4
// speedup vs baseline: 2.4885x; 2.4885x over previous
#include <cuda_runtime.h>
#include <cuda_bf16.h>
#include <cstdint>
#include <cstddef>

#define NSRC 4096
#define NTGT 4096
#define DIM  1024

// ---------------- scratch (__device__ globals; no allocations allowed) -----
__device__ float g_sp[(size_t)NSRC * DIM];
__device__ float g_tp[(size_t)NTGT * DIM];
__device__ float g_sqs[NSRC];
__device__ float g_sqt[NTGT];
__device__ float g_rowsum[NSRC];

__device__ __nv_bfloat16 g_srch[(size_t)NSRC * DIM], g_srcl[(size_t)NSRC * DIM];
__device__ __nv_bfloat16 g_tgth[(size_t)NTGT * DIM], g_tgtl[(size_t)NTGT * DIM];
__device__ __nv_bfloat16 g_Wsh[(size_t)DIM * DIM],   g_Wsl[(size_t)DIM * DIM];
__device__ __nv_bfloat16 g_Wth[(size_t)DIM * DIM],   g_Wtl[(size_t)DIM * DIM];
__device__ __nv_bfloat16 g_sph[(size_t)NSRC * DIM],  g_spl[(size_t)NSRC * DIM];
__device__ __nv_bfloat16 g_tph[(size_t)NTGT * DIM],  g_tpl[(size_t)NTGT * DIM];
__device__ __nv_bfloat16 g_tTh[(size_t)DIM * NTGT],  g_tTl[(size_t)DIM * NTGT];
__device__ __nv_bfloat16 g_Kh[(size_t)NSRC * NTGT],  g_Kl[(size_t)NSRC * NTGT];

// ---------------- helpers ----------------------------------------------------
__device__ __forceinline__ uint32_t smem_to_u32(const void* p) {
    uint32_t a;
    asm("{ .reg .u64 t; cvta.to.shared.u64 t, %1; cvt.u32.u64 %0, t; }" : "=r"(a) : "l"(p));
    return a;
}
__device__ __forceinline__ uint32_t lds_u32(uint32_t a) {
    uint32_t v;
    asm volatile("ld.shared.b32 %0, [%1];" : "=r"(v) : "r"(a));
    return v;
}
__device__ __forceinline__ void cp_async16(uint32_t dst, const void* src) {
    asm volatile("cp.async.cg.shared.global [%0], [%1], 16;" :: "r"(dst), "l"(src) : "memory");
}
__device__ __forceinline__ void mma_bf16(float* c, const uint32_t* a, const uint32_t* b) {
    asm volatile(
        "mma.sync.aligned.m16n8k16.row.col.f32.bf16.bf16.f32 "
        "{%0,%1,%2,%3}, {%4,%5,%6,%7}, {%8,%9}, {%0,%1,%2,%3};"
        : "+f"(c[0]), "+f"(c[1]), "+f"(c[2]), "+f"(c[3])
        : "r"(a[0]), "r"(a[1]), "r"(a[2]), "r"(a[3]), "r"(b[0]), "r"(b[1]));
}
__device__ __forceinline__ void f32_split(float x, unsigned short& h, unsigned short& l) {
    __nv_bfloat16 bh = __float2bfloat16(x);
    float r = x - __bfloat162float(bh);
    __nv_bfloat16 bl = __float2bfloat16(r);
    h = __bfloat16_as_ushort(bh);
    l = __bfloat16_as_ushort(bl);
}

// ---------------- warp-MMA split-bf16 NT GEMM -------------------------------
// C[r,c] = sum_k A[r,k]*B[c,k]; A,B given as bf16 hi/lo pairs; fp32 accum via
// three passes (hh + hl + lh). CTA tile 128x128, BK=32, double-buffered cp.async.
#define EPI_NONE 0
#define EPI_BIAS 1
#define EPI_COST 2

#define BK 32
#define ROW_BYTES 80                       // 32 halves (64B) + 16B pad
enum { TILE_BYTES = 128 * ROW_BYTES,       // 10240
       BUF_BYTES  = 4 * TILE_BYTES,        // Ah,Al,Bh,Bl
       SMEM_DYN   = 2 * BUF_BYTES };       // 81920

template <int EPI>
__global__ void __launch_bounds__(256, 2) tc_gemm(
    const __nv_bfloat16* __restrict__ Ah, const __nv_bfloat16* __restrict__ Al,
    const __nv_bfloat16* __restrict__ Bh, const __nv_bfloat16* __restrict__ Bl,
    const float* __restrict__ bias,
    const float* __restrict__ sqa, const float* __restrict__ sqb,
    const float* __restrict__ temp,
    float* __restrict__ C,
    __nv_bfloat16* __restrict__ Chb, __nv_bfloat16* __restrict__ Clb,
    int N, int Kdim)
{
    extern __shared__ char dsm[];
    const uint32_t sm0 = smem_to_u32(dsm);
    const int tid = threadIdx.x;
    const int wid = tid >> 5, lane = tid & 31;
    const int warpRow = wid & 1;         // 2 row-warps  (64 rows each)
    const int warpCol = wid >> 1;        // 4 col-warps  (32 cols each)
    const int g  = lane >> 2;            // 0..7
    const int qp = lane & 3;             // 0..3
    const int rowBase = blockIdx.y * 128;
    const int colBase = blockIdx.x * 128;

    const __nv_bfloat16* basep[4] = {
        Ah + (size_t)rowBase * Kdim, Al + (size_t)rowBase * Kdim,
        Bh + (size_t)colBase * Kdim, Bl + (size_t)colBase * Kdim };

    float acc[4][4][4];
#pragma unroll
    for (int mf = 0; mf < 4; mf++)
#pragma unroll
        for (int nf = 0; nf < 4; nf++)
#pragma unroll
            for (int e = 0; e < 4; e++) acc[mf][nf][e] = 0.f;

    const int KC = Kdim / BK;

    // ---- async tile loader: chunk ch -> buffer buf
    auto issue = [&](int ch, int buf) {
        uint32_t sbase = sm0 + (uint32_t)buf * BUF_BYTES;
        int kt = ch * BK;
#pragma unroll
        for (int j = 0; j < 8; j++) {
            int id  = j * 256 + tid;         // 0..2047
            int t   = id >> 9;               // tile 0..3
            int c   = id & 511;
            int row = c >> 2;
            int seg = c & 3;
            const void* src = basep[t] + (size_t)row * Kdim + kt + seg * 8;
            uint32_t dst = sbase + (uint32_t)t * TILE_BYTES + row * ROW_BYTES + seg * 16;
            cp_async16(dst, src);
        }
        asm volatile("cp.async.commit_group;" ::: "memory");
    };

    issue(0, 0);
    for (int ch = 0; ch < KC; ch++) {
        int buf = ch & 1;
        if (ch + 1 < KC) {
            issue(ch + 1, buf ^ 1);
            asm volatile("cp.async.wait_group 1;" ::: "memory");
        } else {
            asm volatile("cp.async.wait_group 0;" ::: "memory");
        }
        __syncthreads();

        uint32_t sb = sm0 + (uint32_t)buf * BUF_BYTES;
#pragma unroll
        for (int ks = 0; ks < 2; ks++) {
            const int k0b = (ks * 16 + qp * 2) * 2;   // byte offset of k0 within row
            // B fragments (all 4 n-frags, hi+lo)
            uint32_t bh[4][2], bl[4][2];
#pragma unroll
            for (int nf = 0; nf < 4; nf++) {
                int n = warpCol * 32 + nf * 8 + g;
                uint32_t off = (uint32_t)n * ROW_BYTES + k0b;
                bh[nf][0] = lds_u32(sb + 2u * TILE_BYTES + off);
                bh[nf][1] = lds_u32(sb + 2u * TILE_BYTES + off + 16);
                bl[nf][0] = lds_u32(sb + 3u * TILE_BYTES + off);
                bl[nf][1] = lds_u32(sb + 3u * TILE_BYTES + off + 16);
            }
#pragma unroll
            for (int mf = 0; mf < 4; mf++) {
                int r0 = warpRow * 64 + mf * 16 + g;
                uint32_t offA = (uint32_t)r0 * ROW_BYTES + k0b;
                uint32_t ah[4], al[4];
                ah[0] = lds_u32(sb + offA);
                ah[1] = lds_u32(sb + offA + 8 * ROW_BYTES);
                ah[2] = lds_u32(sb + offA + 16);
                ah[3] = lds_u32(sb + offA + 8 * ROW_BYTES + 16);
                al[0] = lds_u32(sb + TILE_BYTES + offA);
                al[1] = lds_u32(sb + TILE_BYTES + offA + 8 * ROW_BYTES);
                al[2] = lds_u32(sb + TILE_BYTES + offA + 16);
                al[3] = lds_u32(sb + TILE_BYTES + offA + 8 * ROW_BYTES + 16);
#pragma unroll
                for (int nf = 0; nf < 4; nf++) {
                    mma_bf16(acc[mf][nf], ah, bh[nf]);   // hh
                    mma_bf16(acc[mf][nf], ah, bl[nf]);   // hl
                    mma_bf16(acc[mf][nf], al, bh[nf]);   // lh
                }
            }
        }
        __syncthreads();
    }

    // ---- epilogue -----------------------------------------------------------
    const float invT = (EPI == EPI_COST) ? (1.0f / temp[0]) : 0.f;
#pragma unroll
    for (int mf = 0; mf < 4; mf++) {
        int r0 = rowBase + warpRow * 64 + mf * 16 + g;
#pragma unroll
        for (int half = 0; half < 2; half++) {
            int r = r0 + half * 8;
            float sa = (EPI == EPI_COST) ? sqa[r] : 0.f;
#pragma unroll
            for (int nf = 0; nf < 4; nf++) {
                int c0 = colBase + warpCol * 32 + nf * 8 + qp * 2;
                float v0 = acc[mf][nf][half * 2 + 0];
                float v1 = acc[mf][nf][half * 2 + 1];
                if (EPI == EPI_COST) {
                    float d20 = sa + sqb[c0 + 0] - 2.0f * v0;
                    float d21 = sa + sqb[c0 + 1] - 2.0f * v1;
                    v0 = __expf(-sqrtf(fmaxf(d20, 0.0f)) * invT);
                    v1 = __expf(-sqrtf(fmaxf(d21, 0.0f)) * invT);
                } else if (EPI == EPI_BIAS) {
                    v0 += bias[c0 + 0];
                    v1 += bias[c0 + 1];
                }
                *(float2*)(C + (size_t)r * N + c0) = make_float2(v0, v1);
                if (EPI == EPI_BIAS) {
                    unsigned short h0, h1, l0, l1;
                    f32_split(v0, h0, l0);
                    f32_split(v1, h1, l1);
                    *(uint32_t*)(Chb + (size_t)r * N + c0) =
                        (uint32_t)h0 | ((uint32_t)h1 << 16);
                    *(uint32_t*)(Clb + (size_t)r * N + c0) =
                        (uint32_t)l0 | ((uint32_t)l1 << 16);
                }
            }
        }
    }
}

// ---------------- small kernels ---------------------------------------------
__global__ __launch_bounds__(256) void split_kernel(
    const float* __restrict__ in, __nv_bfloat16* __restrict__ oh,
    __nv_bfloat16* __restrict__ ol, size_t n4)
{
    size_t i = (size_t)blockIdx.x * 256 + threadIdx.x;
    if (i >= n4) return;
    float4 v = ((const float4*)in)[i];
    unsigned short h0, h1, h2, h3, l0, l1, l2, l3;
    f32_split(v.x, h0, l0); f32_split(v.y, h1, l1);
    f32_split(v.z, h2, l2); f32_split(v.w, h3, l3);
    ((uint2*)oh)[i] = make_uint2((uint32_t)h0 | ((uint32_t)h1 << 16),
                                 (uint32_t)h2 | ((uint32_t)h3 << 16));
    ((uint2*)ol)[i] = make_uint2((uint32_t)l0 | ((uint32_t)l1 << 16),
                                 (uint32_t)l2 | ((uint32_t)l3 << 16));
}

// target [NTGT][DIM] fp32 -> hi/lo bf16 [DIM][NTGT]
__global__ void transpose_split(const float* __restrict__ in,
                                __nv_bfloat16* __restrict__ oh,
                                __nv_bfloat16* __restrict__ ol)
{
    __shared__ float t[32][33];
    int x  = blockIdx.x * 32 + threadIdx.x;   // DIM index
    int y0 = blockIdx.y * 32;                 // NTGT base
#pragma unroll
    for (int i = 0; i < 4; i++)
        t[threadIdx.y + i * 8][threadIdx.x] = in[(size_t)(y0 + threadIdx.y + i * 8) * DIM + x];
    __syncthreads();
    int ox  = y0 + threadIdx.x;
    int oy0 = blockIdx.x * 32;
#pragma unroll
    for (int i = 0; i < 4; i++) {
        float v = t[threadIdx.x][threadIdx.y + i * 8];
        unsigned short h, l;
        f32_split(v, h, l);
        size_t o = (size_t)(oy0 + threadIdx.y + i * 8) * NTGT + ox;
        oh[o] = __ushort_as_bfloat16(h);
        ol[o] = __ushort_as_bfloat16(l);
    }
}

template <bool SQ>
__global__ __launch_bounds__(256) void row_reduce(
    const float* __restrict__ X, float* __restrict__ out, int cols)
{
    const int row = blockIdx.x;
    const float4* p = reinterpret_cast<const float4*>(X + (size_t)row * cols);
    const int n4 = cols >> 2;
    float s = 0.f;
    for (int j = threadIdx.x; j < n4; j += 256) {
        float4 v = p[j];
        if (SQ) s += v.x * v.x + v.y * v.y + v.z * v.z + v.w * v.w;
        else    s += v.x + v.y + v.z + v.w;
    }
    __shared__ float red[256];
    red[threadIdx.x] = s;
    __syncthreads();
#pragma unroll
    for (int st = 128; st > 0; st >>= 1) {
        if (threadIdx.x < st) red[threadIdx.x] += red[threadIdx.x + st];
        __syncthreads();
    }
    if (threadIdx.x == 0) out[row] = red[0];
}

// normalize K rows in place (fp32) and emit bf16 hi/lo split of K
__global__ __launch_bounds__(256) void normalize_split(
    float* __restrict__ Kmat, const float* __restrict__ rowsum,
    __nv_bfloat16* __restrict__ Kh, __nv_bfloat16* __restrict__ Kl)
{
    size_t idx = (size_t)blockIdx.x * 256 + threadIdx.x;   // float4 index
    size_t total4 = ((size_t)NSRC * NTGT) >> 2;
    if (idx >= total4) return;
    int row = (int)(idx >> 10);                            // 1024 float4 per row
    float inv = 1.0f / rowsum[row];
    float4* p = (float4*)Kmat + idx;
    float4 v = *p;
    v.x *= inv; v.y *= inv; v.z *= inv; v.w *= inv;
    *p = v;
    unsigned short h0, h1, h2, h3, l0, l1, l2, l3;
    f32_split(v.x, h0, l0); f32_split(v.y, h1, l1);
    f32_split(v.z, h2, l2); f32_split(v.w, h3, l3);
    ((uint2*)Kh)[idx] = make_uint2((uint32_t)h0 | ((uint32_t)h1 << 16),
                                   (uint32_t)h2 | ((uint32_t)h3 << 16));
    ((uint2*)Kl)[idx] = make_uint2((uint32_t)l0 | ((uint32_t)l1 << 16),
                                   (uint32_t)l2 | ((uint32_t)l3 << 16));
}

// ---------------- launch -----------------------------------------------------
extern "C" void kernel_launch(void* const* d_in, const int* in_sizes, int n_in,
                              void* d_out, int out_size)
{
    const float* source = (const float*)d_in[0];
    const float* target = (const float*)d_in[1];
    const float* W_src  = (const float*)d_in[2];
    const float* b_src  = (const float*)d_in[3];
    const float* W_tgt  = (const float*)d_in[4];
    const float* b_tgt  = (const float*)d_in[5];
    const float* temp   = (const float*)d_in[6];

    float* aligned = (float*)d_out;                       // [NSRC, DIM]
    float* Kout    = (float*)d_out + (size_t)NSRC * DIM;  // [NSRC, NTGT]

    float *sp, *tp, *sqs, *sqt, *rs;
    __nv_bfloat16 *srch, *srcl, *tgth, *tgtl, *Wsh, *Wsl, *Wth, *Wtl;
    __nv_bfloat16 *sph, *spl, *tph, *tpl, *tTh, *tTl, *Kh, *Kl;
    cudaGetSymbolAddress((void**)&sp,  g_sp);
    cudaGetSymbolAddress((void**)&tp,  g_tp);
    cudaGetSymbolAddress((void**)&sqs, g_sqs);
    cudaGetSymbolAddress((void**)&sqt, g_sqt);
    cudaGetSymbolAddress((void**)&rs,  g_rowsum);
    cudaGetSymbolAddress((void**)&srch, g_srch); cudaGetSymbolAddress((void**)&srcl, g_srcl);
    cudaGetSymbolAddress((void**)&tgth, g_tgth); cudaGetSymbolAddress((void**)&tgtl, g_tgtl);
    cudaGetSymbolAddress((void**)&Wsh,  g_Wsh);  cudaGetSymbolAddress((void**)&Wsl,  g_Wsl);
    cudaGetSymbolAddress((void**)&Wth,  g_Wth);  cudaGetSymbolAddress((void**)&Wtl,  g_Wtl);
    cudaGetSymbolAddress((void**)&sph,  g_sph);  cudaGetSymbolAddress((void**)&spl,  g_spl);
    cudaGetSymbolAddress((void**)&tph,  g_tph);  cudaGetSymbolAddress((void**)&tpl,  g_tpl);
    cudaGetSymbolAddress((void**)&tTh,  g_tTh);  cudaGetSymbolAddress((void**)&tTl,  g_tTl);
    cudaGetSymbolAddress((void**)&Kh,   g_Kh);   cudaGetSymbolAddress((void**)&Kl,   g_Kl);

    cudaFuncSetAttribute(tc_gemm<EPI_BIAS>, cudaFuncAttributeMaxDynamicSharedMemorySize, SMEM_DYN);
    cudaFuncSetAttribute(tc_gemm<EPI_COST>, cudaFuncAttributeMaxDynamicSharedMemorySize, SMEM_DYN);
    cudaFuncSetAttribute(tc_gemm<EPI_NONE>, cudaFuncAttributeMaxDynamicSharedMemorySize, SMEM_DYN);

    // 1) split inputs to bf16 hi/lo
    split_kernel<<<(NSRC * DIM / 4 + 255) / 256, 256>>>(source, srch, srcl, (size_t)NSRC * DIM / 4);
    split_kernel<<<(NTGT * DIM / 4 + 255) / 256, 256>>>(target, tgth, tgtl, (size_t)NTGT * DIM / 4);
    split_kernel<<<(DIM * DIM / 4 + 255) / 256, 256>>>(W_src, Wsh, Wsl, (size_t)DIM * DIM / 4);
    split_kernel<<<(DIM * DIM / 4 + 255) / 256, 256>>>(W_tgt, Wth, Wtl, (size_t)DIM * DIM / 4);
    transpose_split<<<dim3(DIM / 32, NTGT / 32), dim3(32, 8)>>>(target, tTh, tTl);

    // 2) projections: sp = source @ W_src^T + b_src (also emits bf16 split of sp)
    tc_gemm<EPI_BIAS><<<dim3(DIM / 128, NSRC / 128), 256, SMEM_DYN>>>(
        srch, srcl, Wsh, Wsl, b_src, nullptr, nullptr, nullptr, sp, sph, spl, DIM, DIM);
    tc_gemm<EPI_BIAS><<<dim3(DIM / 128, NTGT / 128), 256, SMEM_DYN>>>(
        tgth, tgtl, Wth, Wtl, b_tgt, nullptr, nullptr, nullptr, tp, tph, tpl, DIM, DIM);

    // 3) squared norms
    row_reduce<true><<<NSRC, 256>>>(sp, sqs, DIM);
    row_reduce<true><<<NTGT, 256>>>(tp, sqt, DIM);

    // 4) K (unnormalized) = exp(-cdist/T) via split-bf16 MMA + fused epilogue
    tc_gemm<EPI_COST><<<dim3(NTGT / 128, NSRC / 128), 256, SMEM_DYN>>>(
        sph, spl, tph, tpl, nullptr, sqs, sqt, temp, Kout, nullptr, nullptr, NTGT, DIM);

    // 5) row sums + normalize (also emits bf16 split of K)
    row_reduce<false><<<NSRC, 256>>>(Kout, rs, NTGT);
    normalize_split<<<(int)(((size_t)NSRC * NTGT / 4 + 255) / 256), 256>>>(Kout, rs, Kh, Kl);

    // 6) aligned = K @ target  (NT with B = target^T, pre-split)
    tc_gemm<EPI_NONE><<<dim3(DIM / 128, NSRC / 128), 256, SMEM_DYN>>>(
        Kh, Kl, tTh, tTl, nullptr, nullptr, nullptr, nullptr, aligned, nullptr, nullptr,
        DIM, NTGT);
}